// round 1
// baseline (speedup 1.0000x reference)
#include <cuda_runtime.h>

// ---------------- scratch (static device globals; no allocation) ----------------
__device__ float d_h1[8 * 256 * 1024];      // after dup conv  (8MB)
__device__ float d_h2[8 * 64 * 2048];       // after c1 conv   (4MB)
__device__ float d_xx[8 * 2048];            // per-point squared norms
__device__ float d_g1[8 * 64];              // global max feature
__device__ float d_g2[8 * 128];             // after g-path MLP
__device__ int   d_idx[8 * 2048 * 4];       // top-4 neighbor indices
__device__ float d_feat[8 * 128 * 8192];    // edge features     (32MB)
__device__ float d_fa[8 * 64 * 8192];       // ping              (16MB)
__device__ float d_fb[8 * 64 * 8192];       // pong              (16MB)
__device__ float d_local[8 * 64 * 2048];    // max over k        (4MB)
__device__ float d_final[8 * 192 * 2048];   // concat            (12MB)
__device__ float d_h4[8 * 256 * 2048];      // head hidden       (16MB)

// ---------------- generic tiled GEMM: C[o,n] = relu_opt((sum_c A[o,c]*B[c,n])*s[o]+bias[o])
// tile 64x64, Ktile 16, 256 threads, 4x4 micro-tile. O,N multiples of 64; K multiple of 16.
__global__ void __launch_bounds__(256) gemm_sbr(
    const float* __restrict__ A, const float* __restrict__ B, float* __restrict__ C,
    const float* __restrict__ scale, const float* __restrict__ bias,
    int K, int N, long sB, long sC)
{
    __shared__ float As[16][64];
    __shared__ float Bs[16][64];
    const int bz = blockIdx.z;
    const float* Bp = B + (long)bz * sB;
    float* Cp = C + (long)bz * sC;
    const int o0 = blockIdx.y * 64;
    const int n0 = blockIdx.x * 64;
    const int tid = threadIdx.x;
    const int tx = tid & 15, ty = tid >> 4;

    const int ar = tid >> 2;                // 0..63 (A row within tile)
    const int aq = (tid & 3) * 4;           // 0..12 (A k offset)
    const int bk = tid >> 4;                // 0..15 (B k row)
    const int bn = (tid & 15) * 4;          // 0..60 (B n offset)

    float acc[4][4];
#pragma unroll
    for (int i = 0; i < 4; ++i)
#pragma unroll
        for (int j = 0; j < 4; ++j) acc[i][j] = 0.f;

    for (int k0 = 0; k0 < K; k0 += 16) {
        float4 av = *(const float4*)&A[(long)(o0 + ar) * K + k0 + aq];
        As[aq + 0][ar] = av.x;
        As[aq + 1][ar] = av.y;
        As[aq + 2][ar] = av.z;
        As[aq + 3][ar] = av.w;
        *(float4*)&Bs[bk][bn] = *(const float4*)&Bp[(long)(k0 + bk) * N + n0 + bn];
        __syncthreads();
#pragma unroll
        for (int k = 0; k < 16; ++k) {
            float4 a = *(const float4*)&As[k][ty * 4];
            float4 b = *(const float4*)&Bs[k][tx * 4];
            acc[0][0] = fmaf(a.x, b.x, acc[0][0]);
            acc[0][1] = fmaf(a.x, b.y, acc[0][1]);
            acc[0][2] = fmaf(a.x, b.z, acc[0][2]);
            acc[0][3] = fmaf(a.x, b.w, acc[0][3]);
            acc[1][0] = fmaf(a.y, b.x, acc[1][0]);
            acc[1][1] = fmaf(a.y, b.y, acc[1][1]);
            acc[1][2] = fmaf(a.y, b.z, acc[1][2]);
            acc[1][3] = fmaf(a.y, b.w, acc[1][3]);
            acc[2][0] = fmaf(a.z, b.x, acc[2][0]);
            acc[2][1] = fmaf(a.z, b.y, acc[2][1]);
            acc[2][2] = fmaf(a.z, b.z, acc[2][2]);
            acc[2][3] = fmaf(a.z, b.w, acc[2][3]);
            acc[3][0] = fmaf(a.w, b.x, acc[3][0]);
            acc[3][1] = fmaf(a.w, b.y, acc[3][1]);
            acc[3][2] = fmaf(a.w, b.z, acc[3][2]);
            acc[3][3] = fmaf(a.w, b.w, acc[3][3]);
        }
        __syncthreads();
    }

#pragma unroll
    for (int i = 0; i < 4; ++i) {
        int o = o0 + ty * 4 + i;
        float sv = scale ? scale[o] : 1.0f;
        float bv = bias[o];
        float4 r;
        r.x = fmaxf(fmaf(acc[i][0], sv, bv), 0.f);
        r.y = fmaxf(fmaf(acc[i][1], sv, bv), 0.f);
        r.z = fmaxf(fmaf(acc[i][2], sv, bv), 0.f);
        r.w = fmaxf(fmaf(acc[i][3], sv, bv), 0.f);
        *(float4*)&Cp[(long)o * N + n0 + tx * 4] = r;
    }
}

// ---------------- xx[b,n] = sum_c h2^2 (same FMA chain order as the dot in topk) --------
__global__ void xx_kernel()
{
    int t = blockIdx.x * blockDim.x + threadIdx.x;   // 8*2048
    int b = t >> 11, n = t & 2047;
    const float* h = d_h2 + (long)b * 64 * 2048;
    float acc = 0.f;
#pragma unroll
    for (int c = 0; c < 64; ++c) {
        float v = h[c * 2048 + n];
        acc = fmaf(v, v, acc);
    }
    d_xx[t] = acc;
}

// ---------------- g1[b,c] = max_n h2[b,c,n] ----------------
__global__ void gmax_kernel()
{
    int bc = blockIdx.x;          // 0..511
    int tid = threadIdx.x;        // 128 threads
    const float* p = d_h2 + (long)bc * 2048;
    float m = -1e30f;
    for (int i = tid; i < 2048; i += 128) m = fmaxf(m, p[i]);
    __shared__ float sm[128];
    sm[tid] = m;
    __syncthreads();
    for (int s = 64; s > 0; s >>= 1) {
        if (tid < s) sm[tid] = fmaxf(sm[tid], sm[tid + s]);
        __syncthreads();
    }
    if (tid == 0) d_g1[bc] = sm[0];
}

// ---------------- pairwise distances + stable top-4 ----------------
// grid (16, 8), block 128. Each thread owns point n, scans all m.
__global__ void __launch_bounds__(128) pairwise_topk()
{
    __shared__ float sm[64][128];
    __shared__ float sxx[128];
    const int b = blockIdx.y;
    const int n = blockIdx.x * 128 + threadIdx.x;
    const float* h = d_h2 + (long)b * 64 * 2048;

    float hn[64];
#pragma unroll
    for (int c = 0; c < 64; ++c) hn[c] = h[c * 2048 + n];
    const float xn = d_xx[b * 2048 + n];

    float v0 = -1e30f, v1 = -1e30f, v2 = -1e30f, v3 = -1e30f;
    int i0 = 0, i1 = 0, i2 = 0, i3 = 0;

    for (int m0 = 0; m0 < 2048; m0 += 128) {
        __syncthreads();
#pragma unroll 8
        for (int c = 0; c < 64; ++c)
            sm[c][threadIdx.x] = h[c * 2048 + m0 + threadIdx.x];
        sxx[threadIdx.x] = d_xx[b * 2048 + m0 + threadIdx.x];
        __syncthreads();

        for (int mm = 0; mm < 128; mm += 4) {
            float dA = 0.f, dB = 0.f, dC = 0.f, dD = 0.f;
#pragma unroll
            for (int c = 0; c < 64; ++c) {
                float4 s4 = *(const float4*)&sm[c][mm];   // broadcast across warp
                dA = fmaf(hn[c], s4.x, dA);
                dB = fmaf(hn[c], s4.y, dB);
                dC = fmaf(hn[c], s4.z, dC);
                dD = fmaf(hn[c], s4.w, dD);
            }
#pragma unroll
            for (int j = 0; j < 4; ++j) {
                float dot = (j == 0) ? dA : (j == 1) ? dB : (j == 2) ? dC : dD;
                float pd = fmaf(2.0f, dot, -xn) - sxx[mm + j];
                int m = m0 + mm + j;
                if (pd > v3) {                       // strict > keeps lowest index on ties
                    if (pd > v1) {
                        if (pd > v0) {
                            v3 = v2; i3 = i2; v2 = v1; i2 = i1; v1 = v0; i1 = i0;
                            v0 = pd; i0 = m;
                        } else {
                            v3 = v2; i3 = i2; v2 = v1; i2 = i1;
                            v1 = pd; i1 = m;
                        }
                    } else {
                        if (pd > v2) { v3 = v2; i3 = i2; v2 = pd; i2 = m; }
                        else         { v3 = pd; i3 = m; }
                    }
                }
            }
        }
    }
    int base = (b * 2048 + n) * 4;
    d_idx[base + 0] = i0;
    d_idx[base + 1] = i1;
    d_idx[base + 2] = i2;
    d_idx[base + 3] = i3;
}

// ---------------- build edge features: feat[b,c,(n,k)] ----------------
__global__ void build_feat()
{
    long t = (long)blockIdx.x * blockDim.x + threadIdx.x;   // 8*128*8192
    int k = (int)(t & 3);
    int n = (int)((t >> 2) & 2047);
    int c = (int)((t >> 13) & 127);
    int b = (int)(t >> 20);
    const float* h = d_h2 + (long)b * 64 * 2048;
    float v;
    if (c < 64) {
        int j = d_idx[((long)b * 2048 + n) * 4 + k];
        v = h[c * 2048 + j] - h[c * 2048 + n];
    } else {
        v = h[(c - 64) * 2048 + n];
    }
    d_feat[t] = v;
}

// ---------------- local[b,c,n] = max_k fa[b,c,n*4+k] ----------------
__global__ void local_max()
{
    long t = (long)blockIdx.x * blockDim.x + threadIdx.x;   // 8*64*2048
    const float* p = d_fa + t * 4;
    float m = fmaxf(fmaxf(p[0], p[1]), fmaxf(p[2], p[3]));
    d_local[t] = m;
}

// ---------------- global-feature MLP: 64 -> 128 -> 128 ----------------
__global__ void gpath(const float* __restrict__ W3a, const float* __restrict__ s3a,
                      const float* __restrict__ b3a, const float* __restrict__ W3b,
                      const float* __restrict__ s3b, const float* __restrict__ b3b)
{
    __shared__ float gin[64];
    __shared__ float gmid[128];
    int b = blockIdx.x, tid = threadIdx.x;
    if (tid < 64) gin[tid] = d_g1[b * 64 + tid];
    __syncthreads();
    float acc = 0.f;
#pragma unroll
    for (int c = 0; c < 64; ++c) acc = fmaf(W3a[tid * 64 + c], gin[c], acc);
    gmid[tid] = fmaxf(fmaf(acc, s3a[tid], b3a[tid]), 0.f);
    __syncthreads();
    acc = 0.f;
#pragma unroll
    for (int c = 0; c < 128; ++c) acc = fmaf(W3b[tid * 128 + c], gmid[c], acc);
    d_g2[b * 128 + tid] = fmaxf(fmaf(acc, s3b[tid], b3b[tid]), 0.f);
}

// ---------------- final[b,c,n] = c<64 ? local : broadcast g2 ----------------
__global__ void concat_final()
{
    long t = (long)blockIdx.x * blockDim.x + threadIdx.x;   // 8*192*2048
    int n = (int)(t & 2047);
    int c = (int)((t >> 11) % 192);
    int b = (int)(t / (192 * 2048));
    float v = (c < 64) ? d_local[((long)b * 64 + c) * 2048 + n]
                       : d_g2[b * 128 + (c - 64)];
    d_final[t] = v;
}

// ---------------- head: out[b,o,n] = W4b[o,:] @ h4[b,:,n] + bias ----------------
__global__ void out_kernel(const float* __restrict__ W4b,
                           const float* __restrict__ bias4b,
                           float* __restrict__ out)
{
    int t = blockIdx.x * blockDim.x + threadIdx.x;  // 8*2048
    int b = t >> 11, n = t & 2047;
    const float* h = d_h4 + (long)b * 256 * 2048;
    float a0 = bias4b[0], a1 = bias4b[1], a2 = bias4b[2];
#pragma unroll 4
    for (int c = 0; c < 256; ++c) {
        float hv = h[c * 2048 + n];
        a0 = fmaf(W4b[c], hv, a0);
        a1 = fmaf(W4b[256 + c], hv, a1);
        a2 = fmaf(W4b[512 + c], hv, a2);
    }
    out[((long)b * 3 + 0) * 2048 + n] = a0;
    out[((long)b * 3 + 1) * 2048 + n] = a1;
    out[((long)b * 3 + 2) * 2048 + n] = a2;
}

// ---------------- host launcher ----------------
extern "C" void kernel_launch(void* const* d_in, const int* in_sizes, int n_in,
                              void* d_out, int out_size)
{
    const float* x      = (const float*)d_in[0];
    const float* W_dup  = (const float*)d_in[1];
    const float* s_dup  = (const float*)d_in[2];
    const float* b_dup  = (const float*)d_in[3];
    const float* W_c1   = (const float*)d_in[4];
    const float* s_c1   = (const float*)d_in[5];
    const float* b_c1   = (const float*)d_in[6];
    const float* W2a    = (const float*)d_in[7];
    const float* s2a    = (const float*)d_in[8];
    const float* b2a    = (const float*)d_in[9];
    const float* W2b    = (const float*)d_in[10];
    const float* s2b    = (const float*)d_in[11];
    const float* b2b    = (const float*)d_in[12];
    const float* W2c    = (const float*)d_in[13];
    const float* s2c    = (const float*)d_in[14];
    const float* b2c    = (const float*)d_in[15];
    const float* W3a    = (const float*)d_in[16];
    const float* s3a    = (const float*)d_in[17];
    const float* b3a    = (const float*)d_in[18];
    const float* W3b    = (const float*)d_in[19];
    const float* s3b    = (const float*)d_in[20];
    const float* b3b    = (const float*)d_in[21];
    const float* W4a    = (const float*)d_in[22];
    const float* bias4a = (const float*)d_in[23];
    const float* W4b    = (const float*)d_in[24];
    const float* bias4b = (const float*)d_in[25];

    float *p_h1, *p_h2, *p_feat, *p_fa, *p_fb, *p_final, *p_h4;
    cudaGetSymbolAddress((void**)&p_h1, d_h1);
    cudaGetSymbolAddress((void**)&p_h2, d_h2);
    cudaGetSymbolAddress((void**)&p_feat, d_feat);
    cudaGetSymbolAddress((void**)&p_fa, d_fa);
    cudaGetSymbolAddress((void**)&p_fb, d_fb);
    cudaGetSymbolAddress((void**)&p_final, d_final);
    cudaGetSymbolAddress((void**)&p_h4, d_h4);

    // L1: (256x128) @ x[b](128x1024) -> h1
    gemm_sbr<<<dim3(16, 4, 8), 256>>>(W_dup, x, p_h1, s_dup, b_dup,
                                      128, 1024, 131072L, 262144L);
    // L2: (64x128) @ h1[b] reinterpreted as (128x2048) -> h2
    gemm_sbr<<<dim3(32, 1, 8), 256>>>(W_c1, p_h1, p_h2, s_c1, b_c1,
                                      128, 2048, 262144L, 131072L);
    xx_kernel<<<64, 256>>>();
    gmax_kernel<<<512, 128>>>();
    pairwise_topk<<<dim3(16, 8), 128>>>();
    build_feat<<<32768, 256>>>();
    // conv2a: (64x128) @ feat[b](128x8192) -> fa
    gemm_sbr<<<dim3(128, 1, 8), 256>>>(W2a, p_feat, p_fa, s2a, b2a,
                                       128, 8192, 1048576L, 524288L);
    // conv2b: (64x64) @ fa -> fb
    gemm_sbr<<<dim3(128, 1, 8), 256>>>(W2b, p_fa, p_fb, s2b, b2b,
                                       64, 8192, 524288L, 524288L);
    // conv2c: (64x64) @ fb -> fa
    gemm_sbr<<<dim3(128, 1, 8), 256>>>(W2c, p_fb, p_fa, s2c, b2c,
                                       64, 8192, 524288L, 524288L);
    local_max<<<4096, 256>>>();
    gpath<<<8, 128>>>(W3a, s3a, b3a, W3b, s3b, b3b);
    concat_final<<<12288, 256>>>();
    // head hidden: (256x192) @ final[b](192x2048) -> h4 (bias+relu, no scale)
    gemm_sbr<<<dim3(32, 4, 8), 256>>>(W4a, p_final, p_h4, nullptr, bias4a,
                                      192, 2048, 393216L, 524288L);
    out_kernel<<<64, 256>>>(W4b, bias4b, (float*)d_out);
}